// round 13
// baseline (speedup 1.0000x reference)
#include <cuda_runtime.h>

#define H_DIM  2048
#define O_DIM  2048
#define E_NUM  8
#define R_NUM  16
#define K2_DIM 128           // E*R
#define ALPHA  16.0f
#define M_MAX  4096
#define SPLITS 8

// ---- static scratch (no allocations allowed) ----
__device__ float g_cw[M_MAX * E_NUM];                    // per-token expert weight * ALPHA
__device__ float g_part[SPLITS * M_MAX * K2_DIM];        // split-K partials of x@A^T (16 MB)
__device__ float g_tw[M_MAX * K2_DIM];                   // weighted t  (2 MB)
__device__ float g_bst[K2_DIM * O_DIM];                  // B_w transposed to [E*R, O] (1 MB)

__device__ __forceinline__ unsigned long long pack2(float lo, float hi) {
    unsigned long long r;
    asm("mov.b64 %0, {%1, %2};" : "=l"(r) : "f"(lo), "f"(hi));
    return r;
}
// packed fp32x2 FMA: d.lo += a.lo*b.lo ; d.hi += a.hi*b.hi  (Blackwell FFMA2, 2x FFMA rate)
#define FMA2(d, a, b) asm("fma.rn.f32x2 %0, %1, %2, %0;" : "+l"(d) : "l"(a), "l"(b))

// ============================================================
// Router: logits -> top2 -> renormalized weights (*ALPHA)
// one warp per token
// ============================================================
__global__ void router_kernel(const float* __restrict__ x,
                              const float* __restrict__ gate, int M)
{
    int token = blockIdx.x * 4 + (threadIdx.x >> 5);
    int lane  = threadIdx.x & 31;
    if (token >= M) return;

    const float4* xr = (const float4*)(x + (size_t)token * H_DIM);
    float acc[E_NUM];
#pragma unroll
    for (int e = 0; e < E_NUM; e++) acc[e] = 0.f;

    for (int k4 = lane; k4 < H_DIM / 4; k4 += 32) {
        float4 xv = xr[k4];
#pragma unroll
        for (int e = 0; e < E_NUM; e++) {
            float4 gv = ((const float4*)(gate + (size_t)e * H_DIM))[k4];
            acc[e] += xv.x * gv.x + xv.y * gv.y + xv.z * gv.z + xv.w * gv.w;
        }
    }
#pragma unroll
    for (int e = 0; e < E_NUM; e++) {
#pragma unroll
        for (int off = 16; off > 0; off >>= 1)
            acc[e] += __shfl_xor_sync(0xffffffffu, acc[e], off);
    }

    if (lane == 0) {
        int i1 = 0; float m1 = acc[0];
#pragma unroll
        for (int e = 1; e < E_NUM; e++)
            if (acc[e] > m1) { m1 = acc[e]; i1 = e; }
        int i2 = -1; float m2 = -3.0e38f;
#pragma unroll
        for (int e = 0; e < E_NUM; e++)
            if (e != i1 && acc[e] > m2) { m2 = acc[e]; i2 = e; }
        // softmax -> top2 -> renorm == 2-way softmax over top-2 logits
        float w2 = 1.0f / (1.0f + expf(m1 - m2));
        float w1 = 1.0f - w2;
#pragma unroll
        for (int e = 0; e < E_NUM; e++) {
            float v = 0.f;
            if (e == i1) v = ALPHA * w1;
            else if (e == i2) v = ALPHA * w2;
            g_cw[token * E_NUM + e] = v;
        }
    }
}

// ============================================================
// Transpose B_w [E,O,R] -> g_bst [E*R, O]
// ============================================================
__global__ void bst_kernel(const float* __restrict__ Bw)
{
    int idx = blockIdx.x * 256 + threadIdx.x;        // K2_DIM*O_DIM total
    int k2 = idx >> 11;                              // / O_DIM
    int n  = idx & (O_DIM - 1);
    int e  = k2 >> 4, r = k2 & 15;
    g_bst[idx] = Bw[((size_t)e * O_DIM + n) * R_NUM + r];
}

// ============================================================
// Split-K GEMM: part[sl] = x[:, sl-slice] @ A_stacked^T
// block tile 128(M) x 128(N=E*R), K slice 256, 8x8 thread tile, f32x2 FMA
// ============================================================
__global__ void __launch_bounds__(256) gemm_lora_a_kernel(
    const float* __restrict__ X, const float* __restrict__ AW, int M)
{
    __shared__ __align__(16) float As[2][8][128];
    __shared__ __align__(16) float Bs[2][8][128];

    const int tid = threadIdx.x;
    const int bm = blockIdx.x, sl = blockIdx.y;
    const int m0 = bm * 128;
    const int kbase = sl * (H_DIM / SPLITS);

    const int lrow = tid >> 1;
    const int lc4  = (tid & 1) * 4;

    unsigned long long acc[8][4];
#pragma unroll
    for (int i = 0; i < 8; i++)
#pragma unroll
        for (int j = 0; j < 4; j++) acc[i][j] = 0ULL;

    const int NC = (H_DIM / SPLITS) / 8;   // 32

    {
        float4 xv = *(const float4*)&X[(size_t)(m0 + lrow) * H_DIM + kbase + lc4];
        float4 wv = *(const float4*)&AW[(size_t)lrow * H_DIM + kbase + lc4];
        As[0][lc4 + 0][lrow] = xv.x; As[0][lc4 + 1][lrow] = xv.y;
        As[0][lc4 + 2][lrow] = xv.z; As[0][lc4 + 3][lrow] = xv.w;
        Bs[0][lc4 + 0][lrow] = wv.x; Bs[0][lc4 + 1][lrow] = wv.y;
        Bs[0][lc4 + 2][lrow] = wv.z; Bs[0][lc4 + 3][lrow] = wv.w;
    }
    __syncthreads();

    for (int c = 0; c < NC; c++) {
        int cur = c & 1;
        float4 xv, wv;
        bool have_next = (c + 1 < NC);
        if (have_next) {
            int k = kbase + (c + 1) * 8;
            xv = *(const float4*)&X[(size_t)(m0 + lrow) * H_DIM + k + lc4];
            wv = *(const float4*)&AW[(size_t)lrow * H_DIM + k + lc4];
        }
#pragma unroll
        for (int kk = 0; kk < 8; kk++) {
            const float4* ap = (const float4*)&As[cur][kk][(tid >> 4) * 8];
            float4 a0 = ap[0], a1 = ap[1];
            const unsigned long long* bp =
                (const unsigned long long*)&Bs[cur][kk][(tid & 15) * 8];
            unsigned long long b0 = bp[0], b1 = bp[1], b2 = bp[2], b3 = bp[3];
            float a_[8] = {a0.x, a0.y, a0.z, a0.w, a1.x, a1.y, a1.z, a1.w};
#pragma unroll
            for (int i = 0; i < 8; i++) {
                unsigned long long av = pack2(a_[i], a_[i]);
                FMA2(acc[i][0], av, b0);
                FMA2(acc[i][1], av, b1);
                FMA2(acc[i][2], av, b2);
                FMA2(acc[i][3], av, b3);
            }
        }
        if (have_next) {
            int nb = cur ^ 1;
            As[nb][lc4 + 0][lrow] = xv.x; As[nb][lc4 + 1][lrow] = xv.y;
            As[nb][lc4 + 2][lrow] = xv.z; As[nb][lc4 + 3][lrow] = xv.w;
            Bs[nb][lc4 + 0][lrow] = wv.x; Bs[nb][lc4 + 1][lrow] = wv.y;
            Bs[nb][lc4 + 2][lrow] = wv.z; Bs[nb][lc4 + 3][lrow] = wv.w;
        }
        __syncthreads();
    }

    const int mi = (tid >> 4) * 8;
    const int ni = (tid & 15) * 8;
#pragma unroll
    for (int i = 0; i < 8; i++) {
        union { unsigned long long u; float2 f; } c0, c1, c2, c3;
        c0.u = acc[i][0]; c1.u = acc[i][1]; c2.u = acc[i][2]; c3.u = acc[i][3];
        float4 o0 = make_float4(c0.f.x, c0.f.y, c1.f.x, c1.f.y);
        float4 o1 = make_float4(c2.f.x, c2.f.y, c3.f.x, c3.f.y);
        float* orow = &g_part[((size_t)sl * M + (m0 + mi + i)) * K2_DIM + ni];
        *(float4*)&orow[0] = o0;
        *(float4*)&orow[4] = o1;
    }
}

// ============================================================
// Combine split-K partials and apply cw (already * ALPHA)
// ============================================================
__global__ void combine_kernel(int M)
{
    int idx = blockIdx.x * 256 + threadIdx.x;
    if (idx >= M * K2_DIM) return;
    int m = idx >> 7, j = idx & 127;
    float s = 0.f;
#pragma unroll
    for (int p = 0; p < SPLITS; p++)
        s += g_part[((size_t)p * M + m) * K2_DIM + j];
    g_tw[idx] = s * g_cw[m * E_NUM + (j >> 4)];
}

// ============================================================
// Main fused GEMM: out = x @ W^T  +  tw @ Bst
// block tile 128x128, K = 2048 (x/W) + 128 (lora tail), 8x8 thread tile, f32x2
// ============================================================
__global__ void __launch_bounds__(256) gemm_main_kernel(
    const float* __restrict__ X, const float* __restrict__ W,
    float* __restrict__ OUT, int M)
{
    __shared__ __align__(16) float As[2][8][128];
    __shared__ __align__(16) float Bs[2][8][128];

    const int tid = threadIdx.x;
    const int bm = blockIdx.x, bn = blockIdx.y;
    const int m0 = bm * 128, n0 = bn * 128;

    const int lrow = tid >> 1;           // X / W / tw row loads
    const int lc4  = (tid & 1) * 4;
    const int bkr  = tid >> 5;           // Bst: k-row 0..7
    const int bn4  = (tid & 31) * 4;     // Bst: n offset

    unsigned long long acc[8][4];
#pragma unroll
    for (int i = 0; i < 8; i++)
#pragma unroll
        for (int j = 0; j < 4; j++) acc[i][j] = 0ULL;

    const int NC1 = H_DIM / 8;            // 256
    const int NC  = NC1 + K2_DIM / 8;     // 272

    {
        float4 xv = *(const float4*)&X[(size_t)(m0 + lrow) * H_DIM + lc4];
        float4 wv = *(const float4*)&W[(size_t)(n0 + lrow) * H_DIM + lc4];
        As[0][lc4 + 0][lrow] = xv.x; As[0][lc4 + 1][lrow] = xv.y;
        As[0][lc4 + 2][lrow] = xv.z; As[0][lc4 + 3][lrow] = xv.w;
        Bs[0][lc4 + 0][lrow] = wv.x; Bs[0][lc4 + 1][lrow] = wv.y;
        Bs[0][lc4 + 2][lrow] = wv.z; Bs[0][lc4 + 3][lrow] = wv.w;
    }
    __syncthreads();

    for (int c = 0; c < NC; c++) {
        int cur = c & 1;
        float4 xv, wv;
        bool have_next = (c + 1 < NC);
        bool next_lora = (c + 1 >= NC1);
        if (have_next) {
            if (!next_lora) {
                int k = (c + 1) * 8;
                xv = *(const float4*)&X[(size_t)(m0 + lrow) * H_DIM + k + lc4];
                wv = *(const float4*)&W[(size_t)(n0 + lrow) * H_DIM + k + lc4];
            } else {
                int k2 = (c + 1 - NC1) * 8;
                xv = *(const float4*)&g_tw[(size_t)(m0 + lrow) * K2_DIM + k2 + lc4];
                wv = *(const float4*)&g_bst[(size_t)(k2 + bkr) * O_DIM + n0 + bn4];
            }
        }
#pragma unroll
        for (int kk = 0; kk < 8; kk++) {
            const float4* ap = (const float4*)&As[cur][kk][(tid >> 4) * 8];
            float4 a0 = ap[0], a1 = ap[1];
            const unsigned long long* bp =
                (const unsigned long long*)&Bs[cur][kk][(tid & 15) * 8];
            unsigned long long b0 = bp[0], b1 = bp[1], b2 = bp[2], b3 = bp[3];
            float a_[8] = {a0.x, a0.y, a0.z, a0.w, a1.x, a1.y, a1.z, a1.w};
#pragma unroll
            for (int i = 0; i < 8; i++) {
                unsigned long long av = pack2(a_[i], a_[i]);
                FMA2(acc[i][0], av, b0);
                FMA2(acc[i][1], av, b1);
                FMA2(acc[i][2], av, b2);
                FMA2(acc[i][3], av, b3);
            }
        }
        if (have_next) {
            int nb = cur ^ 1;
            As[nb][lc4 + 0][lrow] = xv.x; As[nb][lc4 + 1][lrow] = xv.y;
            As[nb][lc4 + 2][lrow] = xv.z; As[nb][lc4 + 3][lrow] = xv.w;
            if (!next_lora) {
                Bs[nb][lc4 + 0][lrow] = wv.x; Bs[nb][lc4 + 1][lrow] = wv.y;
                Bs[nb][lc4 + 2][lrow] = wv.z; Bs[nb][lc4 + 3][lrow] = wv.w;
            } else {
                *(float4*)&Bs[nb][bkr][bn4] = wv;   // Bst already [k,n]
            }
        }
        __syncthreads();
    }

    const int mi = (tid >> 4) * 8;
    const int ni = (tid & 15) * 8;
#pragma unroll
    for (int i = 0; i < 8; i++) {
        union { unsigned long long u; float2 f; } c0, c1, c2, c3;
        c0.u = acc[i][0]; c1.u = acc[i][1]; c2.u = acc[i][2]; c3.u = acc[i][3];
        float4 o0 = make_float4(c0.f.x, c0.f.y, c1.f.x, c1.f.y);
        float4 o1 = make_float4(c2.f.x, c2.f.y, c3.f.x, c3.f.y);
        float* orow = &OUT[(size_t)(m0 + mi + i) * O_DIM + n0 + ni];
        *(float4*)&orow[0] = o0;
        *(float4*)&orow[4] = o1;
    }
}

// ============================================================
extern "C" void kernel_launch(void* const* d_in, const int* in_sizes, int n_in,
                              void* d_out, int out_size)
{
    const float* x    = (const float*)d_in[0];   // [B,S,H]
    const float* w    = (const float*)d_in[1];   // [O,H]
    const float* gate = (const float*)d_in[2];   // [E,H]
    const float* aw   = (const float*)d_in[3];   // [E,R,H] == [128,H]
    const float* bw   = (const float*)d_in[4];   // [E,O,R]
    float* out = (float*)d_out;

    int M = in_sizes[0] / H_DIM;                 // 4096

    router_kernel<<<M / 4, 128>>>(x, gate, M);
    bst_kernel<<<(K2_DIM * O_DIM) / 256, 256>>>(bw);
    gemm_lora_a_kernel<<<dim3(M / 128, SPLITS), 256>>>(x, aw, M);
    combine_kernel<<<(M * K2_DIM + 255) / 256, 256>>>(M);
    gemm_main_kernel<<<dim3(M / 128, O_DIM / 128), 256>>>(x, w, out, M);
}

// round 14
// speedup vs baseline: 1.0029x; 1.0029x over previous
#include <cuda_runtime.h>

#define H_DIM  2048
#define O_DIM  2048
#define E_NUM  8
#define R_NUM  16
#define K2_DIM 128           // E*R
#define ALPHA  16.0f
#define M_MAX  4096
#define SPLITS 8

// ---- static scratch (no allocations allowed) ----
__device__ float g_cw[M_MAX * E_NUM];                    // per-token expert weight * ALPHA
__device__ float g_part[SPLITS * M_MAX * K2_DIM];        // split-K partials of x@A^T (16 MB)
__device__ float g_tw[M_MAX * K2_DIM];                   // weighted t  (2 MB)
__device__ float g_bst[K2_DIM * O_DIM];                  // B_w transposed to [E*R, O] (1 MB)

__device__ __forceinline__ unsigned long long pack2(float lo, float hi) {
    unsigned long long r;
    asm("mov.b64 %0, {%1, %2};" : "=l"(r) : "f"(lo), "f"(hi));
    return r;
}
// packed fp32x2 FMA: d.lo += a.lo*b.lo ; d.hi += a.hi*b.hi  (Blackwell FFMA2, 2x FFMA rate)
#define FMA2(d, a, b) asm("fma.rn.f32x2 %0, %1, %2, %0;" : "+l"(d) : "l"(a), "l"(b))

// ============================================================
// Router: logits -> top2 -> renormalized weights (*ALPHA)
// one warp per token
// ============================================================
__global__ void router_kernel(const float* __restrict__ x,
                              const float* __restrict__ gate, int M)
{
    int token = blockIdx.x * 4 + (threadIdx.x >> 5);
    int lane  = threadIdx.x & 31;
    if (token >= M) return;

    const float4* xr = (const float4*)(x + (size_t)token * H_DIM);
    float acc[E_NUM];
#pragma unroll
    for (int e = 0; e < E_NUM; e++) acc[e] = 0.f;

    for (int k4 = lane; k4 < H_DIM / 4; k4 += 32) {
        float4 xv = xr[k4];
#pragma unroll
        for (int e = 0; e < E_NUM; e++) {
            float4 gv = ((const float4*)(gate + (size_t)e * H_DIM))[k4];
            acc[e] += xv.x * gv.x + xv.y * gv.y + xv.z * gv.z + xv.w * gv.w;
        }
    }
#pragma unroll
    for (int e = 0; e < E_NUM; e++) {
#pragma unroll
        for (int off = 16; off > 0; off >>= 1)
            acc[e] += __shfl_xor_sync(0xffffffffu, acc[e], off);
    }

    if (lane == 0) {
        int i1 = 0; float m1 = acc[0];
#pragma unroll
        for (int e = 1; e < E_NUM; e++)
            if (acc[e] > m1) { m1 = acc[e]; i1 = e; }
        int i2 = -1; float m2 = -3.0e38f;
#pragma unroll
        for (int e = 0; e < E_NUM; e++)
            if (e != i1 && acc[e] > m2) { m2 = acc[e]; i2 = e; }
        // softmax -> top2 -> renorm == 2-way softmax over top-2 logits
        float w2 = 1.0f / (1.0f + expf(m1 - m2));
        float w1 = 1.0f - w2;
#pragma unroll
        for (int e = 0; e < E_NUM; e++) {
            float v = 0.f;
            if (e == i1) v = ALPHA * w1;
            else if (e == i2) v = ALPHA * w2;
            g_cw[token * E_NUM + e] = v;
        }
    }
}

// ============================================================
// Transpose B_w [E,O,R] -> g_bst [E*R, O]
// ============================================================
__global__ void bst_kernel(const float* __restrict__ Bw)
{
    int idx = blockIdx.x * 256 + threadIdx.x;        // K2_DIM*O_DIM total
    int k2 = idx >> 11;                              // / O_DIM
    int n  = idx & (O_DIM - 1);
    int e  = k2 >> 4, r = k2 & 15;
    g_bst[idx] = Bw[((size_t)e * O_DIM + n) * R_NUM + r];
}

// ============================================================
// Split-K GEMM: part[sl] = x[:, sl-slice] @ A_stacked^T
// block tile 128(M) x 128(N=E*R), K slice 256, 8x8 thread tile, f32x2 FMA
// ============================================================
__global__ void __launch_bounds__(256) gemm_lora_a_kernel(
    const float* __restrict__ X, const float* __restrict__ AW, int M)
{
    __shared__ __align__(16) float As[2][8][128];
    __shared__ __align__(16) float Bs[2][8][128];

    const int tid = threadIdx.x;
    const int bm = blockIdx.x, sl = blockIdx.y;
    const int m0 = bm * 128;
    const int kbase = sl * (H_DIM / SPLITS);

    const int lrow = tid >> 1;
    const int lc4  = (tid & 1) * 4;

    unsigned long long acc[8][4];
#pragma unroll
    for (int i = 0; i < 8; i++)
#pragma unroll
        for (int j = 0; j < 4; j++) acc[i][j] = 0ULL;

    const int NC = (H_DIM / SPLITS) / 8;   // 32

    {
        float4 xv = *(const float4*)&X[(size_t)(m0 + lrow) * H_DIM + kbase + lc4];
        float4 wv = *(const float4*)&AW[(size_t)lrow * H_DIM + kbase + lc4];
        As[0][lc4 + 0][lrow] = xv.x; As[0][lc4 + 1][lrow] = xv.y;
        As[0][lc4 + 2][lrow] = xv.z; As[0][lc4 + 3][lrow] = xv.w;
        Bs[0][lc4 + 0][lrow] = wv.x; Bs[0][lc4 + 1][lrow] = wv.y;
        Bs[0][lc4 + 2][lrow] = wv.z; Bs[0][lc4 + 3][lrow] = wv.w;
    }
    __syncthreads();

    for (int c = 0; c < NC; c++) {
        int cur = c & 1;
        float4 xv, wv;
        bool have_next = (c + 1 < NC);
        if (have_next) {
            int k = kbase + (c + 1) * 8;
            xv = *(const float4*)&X[(size_t)(m0 + lrow) * H_DIM + k + lc4];
            wv = *(const float4*)&AW[(size_t)lrow * H_DIM + k + lc4];
        }
#pragma unroll
        for (int kk = 0; kk < 8; kk++) {
            const float4* ap = (const float4*)&As[cur][kk][(tid >> 4) * 8];
            float4 a0 = ap[0], a1 = ap[1];
            const unsigned long long* bp =
                (const unsigned long long*)&Bs[cur][kk][(tid & 15) * 8];
            unsigned long long b0 = bp[0], b1 = bp[1], b2 = bp[2], b3 = bp[3];
            float a_[8] = {a0.x, a0.y, a0.z, a0.w, a1.x, a1.y, a1.z, a1.w};
#pragma unroll
            for (int i = 0; i < 8; i++) {
                unsigned long long av = pack2(a_[i], a_[i]);
                FMA2(acc[i][0], av, b0);
                FMA2(acc[i][1], av, b1);
                FMA2(acc[i][2], av, b2);
                FMA2(acc[i][3], av, b3);
            }
        }
        if (have_next) {
            int nb = cur ^ 1;
            As[nb][lc4 + 0][lrow] = xv.x; As[nb][lc4 + 1][lrow] = xv.y;
            As[nb][lc4 + 2][lrow] = xv.z; As[nb][lc4 + 3][lrow] = xv.w;
            Bs[nb][lc4 + 0][lrow] = wv.x; Bs[nb][lc4 + 1][lrow] = wv.y;
            Bs[nb][lc4 + 2][lrow] = wv.z; Bs[nb][lc4 + 3][lrow] = wv.w;
        }
        __syncthreads();
    }

    const int mi = (tid >> 4) * 8;
    const int ni = (tid & 15) * 8;
#pragma unroll
    for (int i = 0; i < 8; i++) {
        union { unsigned long long u; float2 f; } c0, c1, c2, c3;
        c0.u = acc[i][0]; c1.u = acc[i][1]; c2.u = acc[i][2]; c3.u = acc[i][3];
        float4 o0 = make_float4(c0.f.x, c0.f.y, c1.f.x, c1.f.y);
        float4 o1 = make_float4(c2.f.x, c2.f.y, c3.f.x, c3.f.y);
        float* orow = &g_part[((size_t)sl * M + (m0 + mi + i)) * K2_DIM + ni];
        *(float4*)&orow[0] = o0;
        *(float4*)&orow[4] = o1;
    }
}

// ============================================================
// Combine split-K partials and apply cw (already * ALPHA)
// ============================================================
__global__ void combine_kernel(int M)
{
    int idx = blockIdx.x * 256 + threadIdx.x;
    if (idx >= M * K2_DIM) return;
    int m = idx >> 7, j = idx & 127;
    float s = 0.f;
#pragma unroll
    for (int p = 0; p < SPLITS; p++)
        s += g_part[((size_t)p * M + m) * K2_DIM + j];
    g_tw[idx] = s * g_cw[m * E_NUM + (j >> 4)];
}

// ============================================================
// Main fused GEMM: out = x @ W^T  +  tw @ Bst
// block tile 128x128, K = 2048 (x/W) + 128 (lora tail), 8x8 thread tile, f32x2
// ============================================================
__global__ void __launch_bounds__(256) gemm_main_kernel(
    const float* __restrict__ X, const float* __restrict__ W,
    float* __restrict__ OUT, int M)
{
    __shared__ __align__(16) float As[2][8][128];
    __shared__ __align__(16) float Bs[2][8][128];

    const int tid = threadIdx.x;
    const int bm = blockIdx.x, bn = blockIdx.y;
    const int m0 = bm * 128, n0 = bn * 128;

    const int lrow = tid >> 1;           // X / W / tw row loads
    const int lc4  = (tid & 1) * 4;
    const int bkr  = tid >> 5;           // Bst: k-row 0..7
    const int bn4  = (tid & 31) * 4;     // Bst: n offset

    unsigned long long acc[8][4];
#pragma unroll
    for (int i = 0; i < 8; i++)
#pragma unroll
        for (int j = 0; j < 4; j++) acc[i][j] = 0ULL;

    const int NC1 = H_DIM / 8;            // 256
    const int NC  = NC1 + K2_DIM / 8;     // 272

    {
        float4 xv = *(const float4*)&X[(size_t)(m0 + lrow) * H_DIM + lc4];
        float4 wv = *(const float4*)&W[(size_t)(n0 + lrow) * H_DIM + lc4];
        As[0][lc4 + 0][lrow] = xv.x; As[0][lc4 + 1][lrow] = xv.y;
        As[0][lc4 + 2][lrow] = xv.z; As[0][lc4 + 3][lrow] = xv.w;
        Bs[0][lc4 + 0][lrow] = wv.x; Bs[0][lc4 + 1][lrow] = wv.y;
        Bs[0][lc4 + 2][lrow] = wv.z; Bs[0][lc4 + 3][lrow] = wv.w;
    }
    __syncthreads();

    for (int c = 0; c < NC; c++) {
        int cur = c & 1;
        float4 xv, wv;
        bool have_next = (c + 1 < NC);
        bool next_lora = (c + 1 >= NC1);
        if (have_next) {
            if (!next_lora) {
                int k = (c + 1) * 8;
                xv = *(const float4*)&X[(size_t)(m0 + lrow) * H_DIM + k + lc4];
                wv = *(const float4*)&W[(size_t)(n0 + lrow) * H_DIM + k + lc4];
            } else {
                int k2 = (c + 1 - NC1) * 8;
                xv = *(const float4*)&g_tw[(size_t)(m0 + lrow) * K2_DIM + k2 + lc4];
                wv = *(const float4*)&g_bst[(size_t)(k2 + bkr) * O_DIM + n0 + bn4];
            }
        }
#pragma unroll
        for (int kk = 0; kk < 8; kk++) {
            const float4* ap = (const float4*)&As[cur][kk][(tid >> 4) * 8];
            float4 a0 = ap[0], a1 = ap[1];
            const unsigned long long* bp =
                (const unsigned long long*)&Bs[cur][kk][(tid & 15) * 8];
            unsigned long long b0 = bp[0], b1 = bp[1], b2 = bp[2], b3 = bp[3];
            float a_[8] = {a0.x, a0.y, a0.z, a0.w, a1.x, a1.y, a1.z, a1.w};
#pragma unroll
            for (int i = 0; i < 8; i++) {
                unsigned long long av = pack2(a_[i], a_[i]);
                FMA2(acc[i][0], av, b0);
                FMA2(acc[i][1], av, b1);
                FMA2(acc[i][2], av, b2);
                FMA2(acc[i][3], av, b3);
            }
        }
        if (have_next) {
            int nb = cur ^ 1;
            As[nb][lc4 + 0][lrow] = xv.x; As[nb][lc4 + 1][lrow] = xv.y;
            As[nb][lc4 + 2][lrow] = xv.z; As[nb][lc4 + 3][lrow] = xv.w;
            if (!next_lora) {
                Bs[nb][lc4 + 0][lrow] = wv.x; Bs[nb][lc4 + 1][lrow] = wv.y;
                Bs[nb][lc4 + 2][lrow] = wv.z; Bs[nb][lc4 + 3][lrow] = wv.w;
            } else {
                *(float4*)&Bs[nb][bkr][bn4] = wv;   // Bst already [k,n]
            }
        }
        __syncthreads();
    }

    const int mi = (tid >> 4) * 8;
    const int ni = (tid & 15) * 8;
#pragma unroll
    for (int i = 0; i < 8; i++) {
        union { unsigned long long u; float2 f; } c0, c1, c2, c3;
        c0.u = acc[i][0]; c1.u = acc[i][1]; c2.u = acc[i][2]; c3.u = acc[i][3];
        float4 o0 = make_float4(c0.f.x, c0.f.y, c1.f.x, c1.f.y);
        float4 o1 = make_float4(c2.f.x, c2.f.y, c3.f.x, c3.f.y);
        float* orow = &OUT[(size_t)(m0 + mi + i) * O_DIM + n0 + ni];
        *(float4*)&orow[0] = o0;
        *(float4*)&orow[4] = o1;
    }
}

// ============================================================
extern "C" void kernel_launch(void* const* d_in, const int* in_sizes, int n_in,
                              void* d_out, int out_size)
{
    const float* x    = (const float*)d_in[0];   // [B,S,H]
    const float* w    = (const float*)d_in[1];   // [O,H]
    const float* gate = (const float*)d_in[2];   // [E,H]
    const float* aw   = (const float*)d_in[3];   // [E,R,H] == [128,H]
    const float* bw   = (const float*)d_in[4];   // [E,O,R]
    float* out = (float*)d_out;

    int M = in_sizes[0] / H_DIM;                 // 4096

    router_kernel<<<M / 4, 128>>>(x, gate, M);
    bst_kernel<<<(K2_DIM * O_DIM) / 256, 256>>>(bw);
    gemm_lora_a_kernel<<<dim3(M / 128, SPLITS), 256>>>(x, aw, M);
    combine_kernel<<<(M * K2_DIM + 255) / 256, 256>>>(M);
    gemm_main_kernel<<<dim3(M / 128, O_DIM / 128), 256>>>(x, w, out, M);
}